// round 4
// baseline (speedup 1.0000x reference)
#include <cuda_runtime.h>
#include <cstdint>

// Problem constants
#define BB   4
#define TT   2048
#define NC   4096
#define AA   8
#define SINK_ITERS 20
#define EPS_ 1e-5f

#define KSPLIT 16
#define DPART  (NC / KSPLIT)   // 256
#define TOKCTA 32              // tokens per CTA (4 warps x 8 tokens)
#define PROWF  260             // phi smem row stride (floats)
#define PARTW  28              // partial row: 24 logits + ssq + pad

// ---------------- scratch ----------------
__device__ __align__(16) float g_buf[AA * 24 * NC];                 // folded phi, TRANSPOSED [a][k][d]
__device__ __align__(16) float part_buf[KSPLIT * BB * TT * PARTW];  // 14.7 MB
__device__ __align__(16) float W_buf[BB * TT * 16];

// ---------------- helpers ----------------
typedef unsigned long long ull;
__device__ __forceinline__ void ffma2(ull& d, ull a, ull b) {
    asm("fma.rn.f32x2 %0, %1, %2, %0;" : "+l"(d) : "l"(a), "l"(b));
}
__device__ __forceinline__ void fadd2(ull& d, ull a, ull b) {
    asm("add.rn.f32x2 %0, %1, %2;" : "=l"(d) : "l"(a), "l"(b));
}
__device__ __forceinline__ void unpack2(ull u, float& lo, float& hi) {
    asm("mov.b64 {%0, %1}, %2;" : "=f"(lo), "=f"(hi) : "l"(u));
}
__device__ __forceinline__ void cp16(uint32_t dst, const void* src) {
    asm volatile("cp.async.cg.shared.global [%0], [%1], 16;" :: "r"(dst), "l"(src));
}

// ---------------- kernel 1: fold alpha*w*phi -> g_buf[a][k][d] (transposed) ----------------
__global__ void fold_k(const float* __restrict__ wnorm,
                       const float* __restrict__ ppre, const float* __restrict__ ppost,
                       const float* __restrict__ pres,
                       const float* __restrict__ apre, const float* __restrict__ apost,
                       const float* __restrict__ ares) {
    int ad = blockIdx.x * 128 + threadIdx.x;     // a*4096 + d
    if (ad >= AA * NC) return;
    int a = ad >> 12, d = ad & (NC - 1);
    float wv = wnorm[ad];
    float cp = apre[a] * wv, cq = apost[a] * wv, cr = ares[a] * wv;
    float* dst = g_buf + (size_t)a * 24 * NC + d;
    float4 v;
    v = ((const float4*)ppre)[ad];
    dst[0 * NC] = cp * v.x; dst[1 * NC] = cp * v.y; dst[2 * NC] = cp * v.z; dst[3 * NC] = cp * v.w;
    v = ((const float4*)ppost)[ad];
    dst[4 * NC] = cq * v.x; dst[5 * NC] = cq * v.y; dst[6 * NC] = cq * v.z; dst[7 * NC] = cq * v.w;
#pragma unroll
    for (int q = 0; q < 4; ++q) {
        v = ((const float4*)pres)[(size_t)ad * 4 + q];
        dst[(8 + 4 * q) * NC] = cr * v.x; dst[(9 + 4 * q) * NC] = cr * v.y;
        dst[(10 + 4 * q) * NC] = cr * v.z; dst[(11 + 4 * q) * NC] = cr * v.w;
    }
}

// ---------------- kernel 2: partial logits ----------------
// grid = 4096: blockIdx.x = tt*KSPLIT + ks.  128 threads = 4 warps.
// lane = tokgrp(0..3)*8 + s(0..7). Thread owns tokens (w*8+tokgrp) and (w*8+tokgrp+4),
// d-slices {s*4 + 32j}, ALL 24 k. acc[t][k] is f32x2 over (even,odd) d of each pair.
__global__ void __launch_bounds__(128, 3)
logits_k(const float* __restrict__ x, const int* __restrict__ aidx) {
    __shared__ __align__(16) float sphi[24 * PROWF];   // 24.96 KB, loaded once

    const int tid = threadIdx.x;
    const int ks = blockIdx.x & (KSPLIT - 1);
    const int tt = blockIdx.x >> 4;                    // token tile 0..255
    const int b = tt >> 6;
    const int aid = aidx[b];
    const int w = tid >> 5, lane = tid & 31;
    const int tokgrp = lane >> 3, s = lane & 7;

    const float* gb = g_buf + (size_t)aid * 24 * NC + ks * DPART;

    // load phi slice [24][256] into smem (once)
    uint32_t sb = (uint32_t)__cvta_generic_to_shared(sphi);
#pragma unroll
    for (int i = 0; i < 12; ++i) {
        int f = i * 128 + tid;                         // 0..1535
        int k = f >> 6, c4 = f & 63;
        cp16(sb + (k * PROWF + c4 * 4) * 4, gb + (size_t)k * NC + c4 * 4);
    }
    asm volatile("cp.async.commit_group;");

    const int tA = tt * TOKCTA + w * 8 + tokgrp;       // local within batch handled via tt
    const int gtA = tA + 0;                            // tt already spans all batches (256 tiles)
    const int gtB = gtA + 4;
    const float* xA = x + (size_t)gtA * NC + ks * DPART;
    const float* xB = x + (size_t)gtB * NC + ks * DPART;

    ull accA[24], accB[24];
#pragma unroll
    for (int k = 0; k < 24; ++k) { accA[k] = 0ull; accB[k] = 0ull; }
    ull ssqA = 0ull, ssqB = 0ull;

    asm volatile("cp.async.wait_group 0;");
    __syncthreads();

    // prefetch j=0
    ulonglong2 xa = *(const ulonglong2*)(xA + s * 4);
    ulonglong2 xb = *(const ulonglong2*)(xB + s * 4);

    for (int j = 0; j < 8; ++j) {
        ulonglong2 na, nb;
        if (j < 7) {
            na = *(const ulonglong2*)(xA + (j + 1) * 32 + s * 4);
            nb = *(const ulonglong2*)(xB + (j + 1) * 32 + s * 4);
        }
        ffma2(ssqA, xa.x, xa.x); ffma2(ssqA, xa.y, xa.y);
        ffma2(ssqB, xb.x, xb.x); ffma2(ssqB, xb.y, xb.y);
        const float* pcol = sphi + j * 32 + s * 4;
#pragma unroll
        for (int k = 0; k < 24; ++k) {
            ulonglong2 p = *(const ulonglong2*)(pcol + k * PROWF);
            ffma2(accA[k], xa.x, p.x); ffma2(accA[k], xa.y, p.y);
            ffma2(accB[k], xb.x, p.x); ffma2(accB[k], xb.y, p.y);
        }
        xa = na; xb = nb;
    }

    // reduce over the 8 d-slices (lane bits 0..2)
#pragma unroll
    for (int k = 0; k < 24; ++k) {
#pragma unroll
        for (int m = 1; m < 8; m <<= 1) {
            ull o = __shfl_xor_sync(0xffffffffu, accA[k], m);
            fadd2(accA[k], accA[k], o);
            o = __shfl_xor_sync(0xffffffffu, accB[k], m);
            fadd2(accB[k], accB[k], o);
        }
    }
#pragma unroll
    for (int m = 1; m < 8; m <<= 1) {
        ull o = __shfl_xor_sync(0xffffffffu, ssqA, m);
        fadd2(ssqA, ssqA, o);
        o = __shfl_xor_sync(0xffffffffu, ssqB, m);
        fadd2(ssqB, ssqB, o);
    }

    if (s == 0) {
        float outv[26];
#pragma unroll
        for (int k = 0; k < 24; ++k) { float lo, hi; unpack2(accA[k], lo, hi); outv[k] = lo + hi; }
        { float lo, hi; unpack2(ssqA, lo, hi); outv[24] = lo + hi; }
        float* pa = part_buf + ((size_t)ks * (BB * TT) + gtA) * PARTW;
#pragma unroll
        for (int q = 0; q < 6; ++q)
            ((float4*)pa)[q] = make_float4(outv[q*4], outv[q*4+1], outv[q*4+2], outv[q*4+3]);
        pa[24] = outv[24];
#pragma unroll
        for (int k = 0; k < 24; ++k) { float lo, hi; unpack2(accB[k], lo, hi); outv[k] = lo + hi; }
        { float lo, hi; unpack2(ssqB, lo, hi); outv[24] = lo + hi; }
        float* pb = part_buf + ((size_t)ks * (BB * TT) + gtB) * PARTW;
#pragma unroll
        for (int q = 0; q < 6; ++q)
            ((float4*)pb)[q] = make_float4(outv[q*4], outv[q*4+1], outv[q*4+2], outv[q*4+3]);
        pb[24] = outv[24];
    }
}

// ---------------- kernel 3: finalize (reduce splits, sinkhorn -> W) ----------------
__global__ void finalize_k(const float* __restrict__ bpre, const float* __restrict__ bpost,
                           const float* __restrict__ bres, const int* __restrict__ aidx) {
    const int t = blockIdx.x * 128 + threadIdx.x;
    const int aid = aidx[t >> 11];

    float a[24];
#pragma unroll
    for (int k = 0; k < 24; ++k) a[k] = 0.0f;
    float ssq = 0.0f;
#pragma unroll
    for (int ks = 0; ks < KSPLIT; ++ks) {
        const float4* p = (const float4*)(part_buf + ((size_t)ks * (BB * TT) + t) * PARTW);
#pragma unroll
        for (int q = 0; q < 6; ++q) {
            float4 v = p[q];
            a[q * 4 + 0] += v.x; a[q * 4 + 1] += v.y;
            a[q * 4 + 2] += v.z; a[q * 4 + 3] += v.w;
        }
        ssq += p[6].x;
    }
    float rinv = rsqrtf(ssq * (1.0f / 4096.0f) + EPS_);

    float hpre[4], hpost[4];
#pragma unroll
    for (int n = 0; n < 4; ++n)
        hpre[n] = 1.0f / (1.0f + expf(-(a[n] * rinv + bpre[aid * 4 + n])));
#pragma unroll
    for (int n = 0; n < 4; ++n)
        hpost[n] = 2.0f / (1.0f + expf(-(a[4 + n] * rinv + bpost[aid * 4 + n])));

    float m[16];
#pragma unroll
    for (int ij = 0; ij < 16; ++ij)
        m[ij] = expf(a[8 + ij] * rinv + bres[aid * 16 + ij]);

    for (int it = 0; it < SINK_ITERS; ++it) {
#pragma unroll
        for (int i = 0; i < 4; ++i) {
            float r = 1.0f / (m[i * 4] + m[i * 4 + 1] + m[i * 4 + 2] + m[i * 4 + 3]);
            m[i * 4] *= r; m[i * 4 + 1] *= r; m[i * 4 + 2] *= r; m[i * 4 + 3] *= r;
        }
#pragma unroll
        for (int j = 0; j < 4; ++j) {
            float r = 1.0f / (m[j] + m[4 + j] + m[8 + j] + m[12 + j]);
            m[j] *= r; m[4 + j] *= r; m[8 + j] *= r; m[12 + j] *= r;
        }
    }

    float4* wd = (float4*)(W_buf + (size_t)t * 16);
#pragma unroll
    for (int i = 0; i < 4; ++i)
        wd[i] = make_float4(m[i * 4 + 0] + hpost[i] * hpre[0],
                            m[i * 4 + 1] + hpost[i] * hpre[1],
                            m[i * 4 + 2] + hpost[i] * hpre[2],
                            m[i * 4 + 3] + hpost[i] * hpre[3]);
}

// ---------------- kernel 4: out[token] = W @ x[token] ----------------
__global__ void out_k(const float* __restrict__ x, float* __restrict__ out) {
    const int token = blockIdx.x;
    __shared__ float sW[16];
    if (threadIdx.x < 16) sW[threadIdx.x] = W_buf[(size_t)token * 16 + threadIdx.x];
    __syncthreads();
    const float4* xr = (const float4*)(x + (size_t)token * NC);
    float4* orow = (float4*)(out + (size_t)token * NC);
    const int c = threadIdx.x;
    float4 xv0 = xr[c], xv1 = xr[256 + c], xv2 = xr[512 + c], xv3 = xr[768 + c];
#pragma unroll
    for (int i = 0; i < 4; ++i) {
        float w0 = sW[i * 4], w1 = sW[i * 4 + 1], w2 = sW[i * 4 + 2], w3 = sW[i * 4 + 3];
        float4 o;
        o.x = w0 * xv0.x + w1 * xv1.x + w2 * xv2.x + w3 * xv3.x;
        o.y = w0 * xv0.y + w1 * xv1.y + w2 * xv2.y + w3 * xv3.y;
        o.z = w0 * xv0.z + w1 * xv1.z + w2 * xv2.z + w3 * xv3.z;
        o.w = w0 * xv0.w + w1 * xv1.w + w2 * xv2.w + w3 * xv3.w;
        orow[i * 256 + c] = o;
    }
}

// ---------------- launch ----------------
extern "C" void kernel_launch(void* const* d_in, const int* in_sizes, int n_in,
                              void* d_out, int out_size) {
    const float* x     = (const float*)d_in[0];
    const float* wnorm = (const float*)d_in[1];
    const float* ppre  = (const float*)d_in[2];
    const float* ppost = (const float*)d_in[3];
    const float* pres  = (const float*)d_in[4];
    const float* bpre  = (const float*)d_in[5];
    const float* bpost = (const float*)d_in[6];
    const float* bres  = (const float*)d_in[7];
    const float* apre  = (const float*)d_in[8];
    const float* apost = (const float*)d_in[9];
    const float* ares  = (const float*)d_in[10];
    const int*   aidx  = (const int*)d_in[11];
    float* out = (float*)d_out;

    fold_k<<<(AA * NC + 127) / 128, 128>>>(wnorm, ppre, ppost, pres, apre, apost, ares);
    logits_k<<<(BB * TT / TOKCTA) * KSPLIT, 128>>>(x, aidx);
    finalize_k<<<BB * TT / 128, 128>>>(bpre, bpost, bres, aidx);
    out_k<<<BB * TT, 256>>>(x, out);
}